// round 13
// baseline (speedup 1.0000x reference)
#include <cuda_runtime.h>
#include <cuda_bf16.h>
#include <cstdint>

// bf16 HMMA (legacy mma.sync — available on plain compute_103 PTX, unlike tcgen05)
#define MMA(c, a, b0, b1) \
    asm volatile("mma.sync.aligned.m16n8k16.row.col.f32.bf16.bf16.f32 " \
        "{%0,%1,%2,%3}, {%4,%5,%6,%7}, {%8,%9}, {%0,%1,%2,%3};" \
        : "+f"((c)[0]), "+f"((c)[1]), "+f"((c)[2]), "+f"((c)[3]) \
        : "r"((a)[0]), "r"((a)[1]), "r"((a)[2]), "r"((a)[3]), "r"(b0), "r"(b1))

__device__ __forceinline__ void cp16(uint32_t dst, const void* src) {
    asm volatile("cp.async.cg.shared.global [%0], [%1], 16;" :: "r"(dst), "l"(src));
}
__device__ __forceinline__ uint32_t smem_u32(const void* p) {
    uint32_t a;
    asm("{ .reg .u64 t; cvta.to.shared.u64 t, %1; cvt.u32.u64 %0, t; }" : "=r"(a) : "l"(p));
    return a;
}

// Pre-converted weights: [hp][96 rows][256 k] bf16 hi / lo. Row r of head-pair hp:
// hh=r>=48, oc=r-48*hh, head=2hp+hh; oc<16:q, <32:k, else v.
__device__ __nv_bfloat16 gWh[768 * 256];
__device__ __nv_bfloat16 gWl[768 * 256];

__global__ void wconv_kernel(const float* __restrict__ qkw, const float* __restrict__ vw) {
    const int g = blockIdx.x;          // 0..767
    const int k = threadIdx.x;         // 0..255
    const int hp = g / 96, r = g - hp * 96;
    const int hh = (r >= 48) ? 1 : 0;
    const int oc = r - 48 * hh;
    const int head = hp * 2 + hh;
    const float* src = (oc < 16) ? qkw + (head * 16 + oc) * 256
                     : (oc < 32) ? qkw + (256 + head * 16 + (oc - 16)) * 256
                                 : vw + (head * 16 + (oc - 32)) * 256;
    const float v = src[k];
    const __nv_bfloat16 h = __float2bfloat16(v);
    gWh[g * 256 + k] = h;
    gWl[g * 256 + k] = __float2bfloat16(v - __bfloat162float(h));
}

// Shapes: B=64, C=256, H=W=56, WS=7, HEADS=16, DH=16; 49 tokens/window (pad 64).
constexpr int AST = 264;                     // bf16 row stride: 528 B
constexpr int A_SZ = 64 * AST * 2;           // 33792 B
constexpr int B_SZ = 96 * AST * 2;           // 50688 B
constexpr int OFF_AH = 0;
constexpr int OFF_AL = OFF_AH + A_SZ;
constexpr int OFF_BH = OFF_AL + A_SZ;        // 67584
constexpr int OFF_BL = OFF_BH + B_SZ;        // 118272
constexpr int OFF_QT = OFF_BL + B_SZ;        // 168960: q|v [64 rows][60] f32 (rows: hh*32 + (q:0-15 | v:16-31))
constexpr int OFF_KT = OFF_QT + 64 * 60 * 4; // 184320: kt[2][64][20] f32  ([hh][t][d])
constexpr int OFF_ST = OFF_KT + 2 * 64 * 20 * 4; // 194560: st[ah][49][50] f32
constexpr int SMEM_TOTAL = OFF_ST + 2 * 49 * 50 * 4;   // 214160 B
constexpr int QTS = 60;                      // float4-aligned row stride
constexpr int KTS = 20;                      // float4-aligned; conflict-free epilogue stores

// Issue cp.async for head-pair hp's weights (hi+lo), one commit group.
__device__ __forceinline__ void stage_weights(uint32_t sb, int hp, int tid) {
    const __nv_bfloat16* srcH = gWh + hp * 96 * 256;
    const __nv_bfloat16* srcL = gWl + hp * 96 * 256;
    #pragma unroll
    for (int i = 0; i < 6; ++i) {
        const int idx = tid + i * 512;         // 96 rows x 32 chunks of 16 B
        const int r = idx >> 5, c8 = (idx & 31) * 8;
        cp16(sb + OFF_BH + (r * AST + c8) * 2, srcH + r * 256 + c8);
        cp16(sb + OFF_BL + (r * AST + c8) * 2, srcL + r * 256 + c8);
    }
    asm volatile("cp.async.commit_group;" ::: "memory");
}

__global__ __launch_bounds__(512, 1)
void wsa_kernel(const float* __restrict__ x,
                const float* __restrict__ bng, const float* __restrict__ bnb,
                const float* __restrict__ bnm, const float* __restrict__ bnv,
                float* __restrict__ out) {
    extern __shared__ char smem[];
    __nv_bfloat16* Ah = (__nv_bfloat16*)(smem + OFF_AH);
    __nv_bfloat16* Al = (__nv_bfloat16*)(smem + OFF_AL);
    __nv_bfloat16* Bh = (__nv_bfloat16*)(smem + OFF_BH);
    __nv_bfloat16* Bl = (__nv_bfloat16*)(smem + OFF_BL);
    float* qt = (float*)(smem + OFF_QT);     // q (0.25-scaled) and v(ReLU'd), [64][60]
    float* kt = (float*)(smem + OFF_KT);     // k, [hh][t][d] stride KTS
    float* st = (float*)(smem + OFF_ST);     // [ah][j][i] stride 50

    const uint32_t sb = smem_u32(smem);
    const int tid  = threadIdx.x;
    const int lane = tid & 31;
    const int warp = tid >> 5;
    const int wb   = blockIdx.x;
    const int b    = wb >> 6;
    const int n1   = (wb >> 3) & 7;
    const int n2   = wb & 7;

    // Kick off hp=0 weight staging immediately (overlaps the x gather below).
    stage_weights(sb, 0, tid);

    // ---- BN + stage A (tokens) as bf16 hi/lo, row-major [t][k]; 2 thread-halves split t ----
    {
        const int c  = tid & 255;
        const int th = tid >> 8;             // 0: t 0..24, 1: t 25..48
        const float inv = bng[c] / sqrtf(bnv[c] + 1e-6f);
        const float shf = bnb[c] - bnm[c] * inv;
        const float* xb = x + ((size_t)b * 256 + c) * 3136 + n1 * 56 + n2;
        const int tbeg = th ? 25 : 0, tend = th ? 49 : 25;
        for (int t = tbeg; t < tend; ++t) {
            const int ti = t / 7, tj = t - (t / 7) * 7;
            const float v = fmaf(xb[ti * 448 + tj * 8], inv, shf);
            const __nv_bfloat16 h = __float2bfloat16(v);
            Ah[t * AST + c] = h;
            Al[t * AST + c] = __float2bfloat16(v - __bfloat162float(h));
        }
        for (int i = tid; i < 15 * 128; i += 512) {        // zero pad rows 49..63
            const int row = 49 + (i >> 7), cc = (i & 127) * 2;
            *(uint32_t*)&Ah[row * AST + cc] = 0u;
            *(uint32_t*)&Al[row * AST + cc] = 0u;
        }
    }

    // 16 warps: m-tile = (warp&3)*16, n-tile = (warp>>2)*24
    const int m0 = (warp & 3) * 16, n0 = (warp >> 2) * 24;
    float* outb = out + (size_t)b * 256 * 3136 + n1 * 56 + n2;

    for (int hp = 0; hp < 8; ++hp) {           // head pair: heads 2hp, 2hp+1
        asm volatile("cp.async.wait_group 0;" ::: "memory");
        __syncthreads();

        // ---- projection: M64 x N96 x K256, split-bf16; 3 independent acc chains ----
        float ach[3][4], acm[3][4], acl[3][4];
        #pragma unroll
        for (int nt = 0; nt < 3; ++nt)
            #pragma unroll
            for (int e = 0; e < 4; ++e) { ach[nt][e] = 0.f; acm[nt][e] = 0.f; acl[nt][e] = 0.f; }

        const int arow = lane >> 2;
        #pragma unroll 2
        for (int ks = 0; ks < 16; ++ks) {
            const int kk = ks * 16 + 2 * (lane & 3);
            uint32_t ah[4], al[4];
            {
                const int r0 = (m0 + arow) * AST;
                ah[0] = *(const uint32_t*)&Ah[r0 + kk];
                ah[1] = *(const uint32_t*)&Ah[r0 + 8 * AST + kk];
                ah[2] = *(const uint32_t*)&Ah[r0 + kk + 8];
                ah[3] = *(const uint32_t*)&Ah[r0 + 8 * AST + kk + 8];
                al[0] = *(const uint32_t*)&Al[r0 + kk];
                al[1] = *(const uint32_t*)&Al[r0 + 8 * AST + kk];
                al[2] = *(const uint32_t*)&Al[r0 + kk + 8];
                al[3] = *(const uint32_t*)&Al[r0 + 8 * AST + kk + 8];
            }
            #pragma unroll
            for (int nt = 0; nt < 3; ++nt) {
                const int nr = (n0 + nt * 8 + arow) * AST;
                const uint32_t bh0 = *(const uint32_t*)&Bh[nr + kk];
                const uint32_t bh1 = *(const uint32_t*)&Bh[nr + kk + 8];
                const uint32_t bl0 = *(const uint32_t*)&Bl[nr + kk];
                const uint32_t bl1 = *(const uint32_t*)&Bl[nr + kk + 8];
                MMA(ach[nt], ah, bh0, bh1);
                MMA(acm[nt], ah, bl0, bl1);
                MMA(acl[nt], al, bh0, bh1);
            }
        }

        // ---- epilogue: merge chains; q*0.25 -> qt, k -> kt[t][d], v(ReLU) -> qt ----
        #pragma unroll
        for (int nt = 0; nt < 3; ++nt) {
            const int row0 = m0 + arow, row1 = row0 + 8;
            const int col  = n0 + nt * 8 + 2 * (lane & 3);   // even; pairs never straddle class
            const int hh   = col / 48;
            const int cls  = col % 48;                       // <16: q, <32: k, else v
            float c0 = ach[nt][0] + acm[nt][0] + acl[nt][0];
            float c1 = ach[nt][1] + acm[nt][1] + acl[nt][1];
            float c2 = ach[nt][2] + acm[nt][2] + acl[nt][2];
            float c3 = ach[nt][3] + acm[nt][3] + acl[nt][3];
            if (cls < 16) {
                c0 *= 0.25f; c1 *= 0.25f; c2 *= 0.25f; c3 *= 0.25f;
                float* r = qt + (hh * 32 + cls) * QTS;
                if (row0 < 49) { r[row0] = c0; r[QTS + row0] = c1; }
                if (row1 < 49) { r[row1] = c2; r[QTS + row1] = c3; }
            } else if (cls < 32) {
                float* kb = kt + hh * 64 * KTS + (cls - 16);
                if (row0 < 49) { kb[row0 * KTS] = c0; kb[row0 * KTS + 1] = c1; }
                if (row1 < 49) { kb[row1 * KTS] = c2; kb[row1 * KTS + 1] = c3; }
            } else {
                c0 = fmaxf(c0, 0.f); c1 = fmaxf(c1, 0.f);
                c2 = fmaxf(c2, 0.f); c3 = fmaxf(c3, 0.f);
                float* r = qt + (hh * 32 + 16 + (cls - 32)) * QTS;
                if (row0 < 49) { r[row0] = c0; r[QTS + row0] = c1; }
                if (row1 < 49) { r[row1] = c2; r[QTS + row1] = c3; }
            }
        }
        __syncthreads();     // all B-fragment reads + qt/kt writes done

        // Prefetch next head-pair's weights; lands while attention below runs.
        if (hp < 7) stage_weights(sb, hp + 1, tid);

        // ---- S = q @ k^T (0.25 pre-folded); k via float4 broadcasts ----
        {
            const int ah2 = warp >> 3, wq2 = warp & 7;
            const float* qb = qt + (ah2 * 32) * QTS;
            const float* kb = kt + ah2 * 64 * KTS;
            const bool act1 = (lane + 32) < 49;
            float q0[16], q1[16];
            #pragma unroll
            for (int dd = 0; dd < 16; ++dd) {
                q0[dd] = qb[dd * QTS + lane];
                q1[dd] = act1 ? qb[dd * QTS + lane + 32] : 0.f;
            }
            #pragma unroll
            for (int jj = 0; jj < 7; ++jj) {
                const int j = wq2 * 7 + jj;
                if (j < 49) {
                    float s0 = 0.f, s1 = 0.f;
                    #pragma unroll
                    for (int g = 0; g < 4; ++g) {
                        const float4 kv = *(const float4*)&kb[j * KTS + g * 4];  // broadcast
                        s0 = fmaf(kv.x, q0[g*4+0], s0); s1 = fmaf(kv.x, q1[g*4+0], s1);
                        s0 = fmaf(kv.y, q0[g*4+1], s0); s1 = fmaf(kv.y, q1[g*4+1], s1);
                        s0 = fmaf(kv.z, q0[g*4+2], s0); s1 = fmaf(kv.z, q1[g*4+2], s1);
                        s0 = fmaf(kv.w, q0[g*4+3], s0); s1 = fmaf(kv.w, q1[g*4+3], s1);
                    }
                    st[(ah2 * 49 + j) * 50 + lane] = s0;
                    if (act1) st[(ah2 * 49 + j) * 50 + lane + 32] = s1;
                }
            }
        }
        __syncthreads();

        // ---- softmax over j per query i ----
        if (tid < 98) {
            const int ah2 = tid >= 49;
            const int i   = tid - ah2 * 49;
            float* col = st + ah2 * 49 * 50 + i;
            float m = -1e30f;
            #pragma unroll 7
            for (int j = 0; j < 49; ++j) m = fmaxf(m, col[j * 50]);
            float sum = 0.f;
            #pragma unroll 7
            for (int j = 0; j < 49; ++j) {
                const float e = __expf(col[j * 50] - m);
                col[j * 50] = e;
                sum += e;
            }
            const float rs = 1.f / sum;
            #pragma unroll 7
            for (int j = 0; j < 49; ++j) col[j * 50] *= rs;
        }
        __syncthreads();

        // ---- O = P @ V; v float4, P rows hoisted across the two d ----
        {
            const int ah2 = warp >> 3;
            const int d0  = (warp & 7) * 2;
            const float* v0r = qt + (ah2 * 32 + 16 + d0) * QTS;
            const float* v1r = v0r + QTS;
            const float* pr  = st + (ah2 * 49) * 50;
            const int head = hp * 2 + ah2;
            const bool act1 = (lane + 32) < 49;
            float o00 = 0.f, o01 = 0.f, o10 = 0.f, o11 = 0.f;
            #pragma unroll 4
            for (int jc = 0; jc < 48; jc += 4) {
                const float4 v0 = *(const float4*)&v0r[jc];   // broadcast
                const float4 v1 = *(const float4*)&v1r[jc];
                #pragma unroll
                for (int e = 0; e < 4; ++e) {
                    const int j = jc + e;
                    const float p0 = pr[j * 50 + lane];
                    const float p1 = act1 ? pr[j * 50 + lane + 32] : 0.f;
                    const float ve0 = (e == 0) ? v0.x : (e == 1) ? v0.y : (e == 2) ? v0.z : v0.w;
                    const float ve1 = (e == 0) ? v1.x : (e == 1) ? v1.y : (e == 2) ? v1.z : v1.w;
                    o00 = fmaf(ve0, p0, o00); o01 = fmaf(ve0, p1, o01);
                    o10 = fmaf(ve1, p0, o10); o11 = fmaf(ve1, p1, o11);
                }
            }
            {   // j = 48 tail
                const float p0 = pr[48 * 50 + lane];
                const float p1 = act1 ? pr[48 * 50 + lane + 32] : 0.f;
                o00 = fmaf(v0r[48], p0, o00); o01 = fmaf(v0r[48], p1, o01);
                o10 = fmaf(v1r[48], p0, o10); o11 = fmaf(v1r[48], p1, o11);
            }
            const int i0 = lane, ti0 = i0 / 7, tj0 = i0 - (i0 / 7) * 7;
            const size_t ch0 = (size_t)(head * 16 + d0) * 3136;
            const size_t ch1 = ch0 + 3136;
            outb[ch0 + ti0 * 448 + tj0 * 8] = o00;
            outb[ch1 + ti0 * 448 + tj0 * 8] = o10;
            if (act1) {
                const int i1 = lane + 32, ti1 = i1 / 7, tj1 = i1 - (i1 / 7) * 7;
                outb[ch0 + ti1 * 448 + tj1 * 8] = o01;
                outb[ch1 + ti1 * 448 + tj1 * 8] = o11;
            }
        }
        // no trailing barrier: next hp's wait_group + __syncthreads orders qt/kt/st reuse
    }
}

extern "C" void kernel_launch(void* const* d_in, const int* in_sizes, int n_in,
                              void* d_out, int out_size) {
    const float* x   = (const float*)d_in[0];
    const float* g   = (const float*)d_in[1];
    const float* be  = (const float*)d_in[2];
    const float* mu  = (const float*)d_in[3];
    const float* var = (const float*)d_in[4];
    const float* qkw = (const float*)d_in[5];
    const float* vw  = (const float*)d_in[6];
    float* out = (float*)d_out;

    wconv_kernel<<<768, 256>>>(qkw, vw);
    cudaFuncSetAttribute(wsa_kernel, cudaFuncAttributeMaxDynamicSharedMemorySize, SMEM_TOTAL);
    wsa_kernel<<<4096, 512, SMEM_TOTAL>>>(x, g, be, mu, var, out);
}

// round 15
// speedup vs baseline: 1.2349x; 1.2349x over previous
#include <cuda_runtime.h>
#include <cuda_bf16.h>
#include <cstdint>

// bf16 HMMA (legacy mma.sync — available on plain compute_103 PTX, unlike tcgen05)
#define MMA(c, a, b0, b1) \
    asm volatile("mma.sync.aligned.m16n8k16.row.col.f32.bf16.bf16.f32 " \
        "{%0,%1,%2,%3}, {%4,%5,%6,%7}, {%8,%9}, {%0,%1,%2,%3};" \
        : "+f"((c)[0]), "+f"((c)[1]), "+f"((c)[2]), "+f"((c)[3]) \
        : "r"((a)[0]), "r"((a)[1]), "r"((a)[2]), "r"((a)[3]), "r"(b0), "r"(b1))

#define BAR_SYNC(id, cnt)   asm volatile("bar.sync %0, %1;"   :: "r"(id), "r"(cnt) : "memory")
#define BAR_ARRIVE(id, cnt) asm volatile("bar.arrive %0, %1;" :: "r"(id), "r"(cnt) : "memory")
// ids: 1=FULL(qt ready) 2=EMPTY buf0 6=EMPTY buf1 3=B_RDY 4=B_FREE 5=GEMM-init 7=ATT-internal
// All barriers strictly alternate producer-arrive / consumer-sync generations (audited):
// the per-buffer EMPTY split removes the only 2-deep-skew barrier (round-14 deadlock).

__device__ __forceinline__ void cp16(uint32_t dst, const void* src) {
    asm volatile("cp.async.cg.shared.global [%0], [%1], 16;" :: "r"(dst), "l"(src));
}
__device__ __forceinline__ uint32_t smem_u32(const void* p) {
    uint32_t a;
    asm("{ .reg .u64 t; cvta.to.shared.u64 t, %1; cvt.u32.u64 %0, t; }" : "=r"(a) : "l"(p));
    return a;
}

// Pre-converted weights: [hp][96 rows][256 k] bf16 hi / lo.
__device__ __nv_bfloat16 gWh[768 * 256];
__device__ __nv_bfloat16 gWl[768 * 256];

__global__ void wconv_kernel(const float* __restrict__ qkw, const float* __restrict__ vw) {
    const int g = blockIdx.x, k = threadIdx.x;
    const int hp = g / 96, r = g - hp * 96;
    const int hh = (r >= 48) ? 1 : 0;
    const int oc = r - 48 * hh;
    const int head = hp * 2 + hh;
    const float* src = (oc < 16) ? qkw + (head * 16 + oc) * 256
                     : (oc < 32) ? qkw + (256 + head * 16 + (oc - 16)) * 256
                                 : vw + (head * 16 + (oc - 32)) * 256;
    const float v = src[k];
    const __nv_bfloat16 h = __float2bfloat16(v);
    gWh[g * 256 + k] = h;
    gWl[g * 256 + k] = __float2bfloat16(v - __bfloat162float(h));
}

// Shapes: B=64, C=256, H=W=56, WS=7, HEADS=16, DH=16; 49 tokens/window (pad 64).
constexpr int AST = 264;                      // bf16 row stride (132 u32, %32==4 -> conflict-free frags)
constexpr int A_SZ = 64 * AST * 2;            // 33792
constexpr int B_SZ = 96 * AST * 2;            // 50688
constexpr int OFF_AH = 0;
constexpr int OFF_AL = OFF_AH + A_SZ;         // 33792
constexpr int OFF_BH = OFF_AL + A_SZ;         // 67584
constexpr int OFF_BL = OFF_BH + B_SZ;         // 118272
constexpr int OFF_QT = OFF_BL + B_SZ;         // 168960: qt[2 buf][64 rows][52] f32 (rows hh*32 + q0-15|v16-31)
constexpr int QTS   = 52;
constexpr int QT_BUF = 64 * QTS * 4;          // 13312
constexpr int OFF_KT = OFF_QT + 2 * QT_BUF;   // 195584: kt[2 buf][2 hh][49][20] f32
constexpr int KTS   = 20;
constexpr int KT_BUF = 2 * 49 * KTS * 4;      // 7840
constexpr int OFF_ST = OFF_KT + 2 * KT_BUF;   // 211264: st[2][49][50] f32
constexpr int SMEM_TOTAL = OFF_ST + 2 * 49 * 50 * 4;   // 230864

// Stage head-pair hp's weights (hi+lo) with 256 attention threads; one commit group.
__device__ __forceinline__ void stage_weights256(uint32_t sb, int hp, int atid) {
    const __nv_bfloat16* srcH = gWh + hp * 96 * 256;
    const __nv_bfloat16* srcL = gWl + hp * 96 * 256;
    #pragma unroll
    for (int i = 0; i < 12; ++i) {
        const int idx = atid + i * 256;        // 0..3071: 96 rows x 32 chunks of 16 B
        const int r = idx >> 5, c8 = (idx & 31) * 8;
        cp16(sb + OFF_BH + (r * AST + c8) * 2, srcH + r * 256 + c8);
        cp16(sb + OFF_BL + (r * AST + c8) * 2, srcL + r * 256 + c8);
    }
    asm volatile("cp.async.commit_group;" ::: "memory");
}

__global__ __launch_bounds__(512, 1)
void wsa_kernel(const float* __restrict__ x,
                const float* __restrict__ bng, const float* __restrict__ bnb,
                const float* __restrict__ bnm, const float* __restrict__ bnv,
                float* __restrict__ out) {
    extern __shared__ char smem[];
    __nv_bfloat16* Ah = (__nv_bfloat16*)(smem + OFF_AH);
    __nv_bfloat16* Al = (__nv_bfloat16*)(smem + OFF_AL);
    __nv_bfloat16* Bh = (__nv_bfloat16*)(smem + OFF_BH);
    __nv_bfloat16* Bl = (__nv_bfloat16*)(smem + OFF_BL);
    float* st = (float*)(smem + OFF_ST);

    const uint32_t sb = smem_u32(smem);
    const int tid  = threadIdx.x;
    const int lane = tid & 31;
    const int warp = tid >> 5;
    const int wb   = blockIdx.x;
    const int b    = wb >> 6;
    const int n1   = (wb >> 3) & 7;
    const int n2   = wb & 7;
    float* outb = out + (size_t)b * 256 * 3136 + n1 * 56 + n2;

    if (warp >= 8) {
        // ===================== ATTENTION / STAGING GROUP (warps 8-15) =====================
        const int atid = tid - 256;
        const int aw   = warp - 8;

        // Prologue: stage B[0]; signal B_RDY.
        stage_weights256(sb, 0, atid);
        asm volatile("cp.async.wait_group 0;" ::: "memory");
        __threadfence_block();
        BAR_ARRIVE(3, 512);

        for (int hp = 0; hp < 8; ++hp) {
            const int buf = hp & 1;
            float* qtb = (float*)(smem + OFF_QT) + buf * 64 * QTS;
            float* ktb = (float*)(smem + OFF_KT) + buf * 2 * 49 * KTS;

            BAR_SYNC(1, 512);                 // qt[buf] full (GEMM hp done)

            if (hp < 7) {                     // stage B[hp+1] in GEMM(hp+1)-wait's shadow
                BAR_SYNC(4, 512);             // GEMM hp finished reading B
                stage_weights256(sb, hp + 1, atid);
                asm volatile("cp.async.wait_group 0;" ::: "memory");
                __threadfence_block();
                BAR_ARRIVE(3, 512);
            }

            // ---- S = q @ k^T (0.25 pre-folded into q) ----
            {
                const int ah2 = aw >> 2, jg = aw & 3;
                const float* qb = qtb + (ah2 * 32) * QTS;
                const float* kb = ktb + ah2 * 49 * KTS;
                const bool act1 = (lane + 32) < 49;
                float q0[16], q1[16];
                #pragma unroll
                for (int dd = 0; dd < 16; ++dd) {
                    q0[dd] = qb[dd * QTS + lane];
                    q1[dd] = act1 ? qb[dd * QTS + lane + 32] : 0.f;
                }
                #pragma unroll
                for (int jj = 0; jj < 13; ++jj) {
                    const int j = jg * 13 + jj;
                    if (j < 49) {
                        float s0 = 0.f, s1 = 0.f;
                        #pragma unroll
                        for (int g = 0; g < 4; ++g) {
                            const float4 kv = *(const float4*)&kb[j * KTS + g * 4];  // broadcast
                            s0 = fmaf(kv.x, q0[g*4+0], s0); s1 = fmaf(kv.x, q1[g*4+0], s1);
                            s0 = fmaf(kv.y, q0[g*4+1], s0); s1 = fmaf(kv.y, q1[g*4+1], s1);
                            s0 = fmaf(kv.z, q0[g*4+2], s0); s1 = fmaf(kv.z, q1[g*4+2], s1);
                            s0 = fmaf(kv.w, q0[g*4+3], s0); s1 = fmaf(kv.w, q1[g*4+3], s1);
                        }
                        st[(ah2 * 49 + j) * 50 + lane] = s0;
                        if (act1) st[(ah2 * 49 + j) * 50 + lane + 32] = s1;
                    }
                }
            }
            BAR_SYNC(7, 256);

            // ---- softmax over j per query i (cols 0..97) ----
            if (atid < 98) {
                const int ah2 = atid >= 49;
                const int i   = atid - ah2 * 49;
                float* col = st + ah2 * 49 * 50 + i;
                float m = -1e30f;
                #pragma unroll 7
                for (int j = 0; j < 49; ++j) m = fmaxf(m, col[j * 50]);
                float sum = 0.f;
                #pragma unroll 7
                for (int j = 0; j < 49; ++j) {
                    const float e = __expf(col[j * 50] - m);
                    col[j * 50] = e;
                    sum += e;
                }
                const float rs = 1.f / sum;
                #pragma unroll 7
                for (int j = 0; j < 49; ++j) col[j * 50] *= rs;
            }
            BAR_SYNC(7, 256);

            // ---- O = P @ V -> scatter; each warp: 1 head x 4 d ----
            {
                const int ah2 = aw >> 2;
                const int d0  = (aw & 3) * 4;
                const float* pr = st + (ah2 * 49) * 50;
                const float* vr = qtb + (ah2 * 32 + 16 + d0) * QTS;
                const int head = hp * 2 + ah2;
                const bool act1 = (lane + 32) < 49;
                float o[4][2];
                #pragma unroll
                for (int e = 0; e < 4; ++e) { o[e][0] = 0.f; o[e][1] = 0.f; }
                #pragma unroll 3
                for (int jc = 0; jc < 48; jc += 4) {
                    float4 v[4];
                    #pragma unroll
                    for (int e = 0; e < 4; ++e) v[e] = *(const float4*)&vr[e * QTS + jc];
                    #pragma unroll
                    for (int e2 = 0; e2 < 4; ++e2) {
                        const int j = jc + e2;
                        const float p0 = pr[j * 50 + lane];
                        const float p1 = act1 ? pr[j * 50 + lane + 32] : 0.f;
                        #pragma unroll
                        for (int e = 0; e < 4; ++e) {
                            const float ve = (e2 == 0) ? v[e].x : (e2 == 1) ? v[e].y
                                          : (e2 == 2) ? v[e].z : v[e].w;
                            o[e][0] = fmaf(ve, p0, o[e][0]);
                            o[e][1] = fmaf(ve, p1, o[e][1]);
                        }
                    }
                }
                {   // j = 48 tail
                    const float p0 = pr[48 * 50 + lane];
                    const float p1 = act1 ? pr[48 * 50 + lane + 32] : 0.f;
                    #pragma unroll
                    for (int e = 0; e < 4; ++e) {
                        o[e][0] = fmaf(vr[e * QTS + 48], p0, o[e][0]);
                        o[e][1] = fmaf(vr[e * QTS + 48], p1, o[e][1]);
                    }
                }
                const int i0 = lane, ti0 = i0 / 7, tj0 = i0 - (i0 / 7) * 7;
                const int i1 = lane + 32, ti1 = i1 / 7, tj1 = i1 - (i1 / 7) * 7;
                #pragma unroll
                for (int e = 0; e < 4; ++e) {
                    const size_t ch = (size_t)(head * 16 + d0 + e) * 3136;
                    outb[ch + ti0 * 448 + tj0 * 8] = o[e][0];
                    if (act1) outb[ch + ti1 * 448 + tj1 * 8] = o[e][1];
                }
            }

            if (hp < 6) {                     // release qt[buf] (all qt/kt/st reads consumed above)
                __threadfence_block();
                BAR_ARRIVE(2 + buf * 4, 512); // 2: buf0, 6: buf1
            }
        }
    } else {
        // ===================== GEMM GROUP (warps 0-7) =====================
        // Stage A: channel c = tid (0..255), all 49 tokens, bf16 hi/lo split.
        {
            const int c = tid;
            const float inv = bng[c] / sqrtf(bnv[c] + 1e-6f);
            const float shf = bnb[c] - bnm[c] * inv;
            const float* xb = x + ((size_t)b * 256 + c) * 3136 + n1 * 56 + n2;
            #pragma unroll 7
            for (int t = 0; t < 49; ++t) {
                const int ti = t / 7, tj = t - (t / 7) * 7;
                const float v = fmaf(xb[ti * 448 + tj * 8], inv, shf);
                const __nv_bfloat16 h = __float2bfloat16(v);
                Ah[t * AST + c] = h;
                Al[t * AST + c] = __float2bfloat16(v - __bfloat162float(h));
            }
            for (int i = tid; i < 15 * 128; i += 256) {     // zero pad rows 49..63 (k 0..255)
                const int row = 49 + (i >> 7), cc = (i & 127) * 2;
                *(uint32_t*)&Ah[row * AST + cc] = 0u;
                *(uint32_t*)&Al[row * AST + cc] = 0u;
            }
        }
        BAR_SYNC(5, 256);                     // A visible to all GEMM warps

        const int m0 = (warp & 1) * 32;
        const int n0 = (warp >> 1) * 24;
        const int arow = lane >> 2;

        for (int hp = 0; hp < 8; ++hp) {
            const int buf = hp & 1;
            float* qtb = (float*)(smem + OFF_QT) + buf * 64 * QTS;
            float* ktb = (float*)(smem + OFF_KT) + buf * 2 * 49 * KTS;

            BAR_SYNC(3, 512);                 // B[hp] staged

            float acc[2][3][4];
            #pragma unroll
            for (int mt = 0; mt < 2; ++mt)
                #pragma unroll
                for (int nt = 0; nt < 3; ++nt)
                    #pragma unroll
                    for (int e = 0; e < 4; ++e) acc[mt][nt][e] = 0.f;

            #pragma unroll 2
            for (int ks = 0; ks < 16; ++ks) {
                const int kk = ks * 16 + 2 * (lane & 3);
                uint32_t ah[2][4], al[2][4];
                #pragma unroll
                for (int mt = 0; mt < 2; ++mt) {
                    const int r0 = (m0 + mt * 16 + arow) * AST;
                    ah[mt][0] = *(const uint32_t*)&Ah[r0 + kk];
                    ah[mt][1] = *(const uint32_t*)&Ah[r0 + 8 * AST + kk];
                    ah[mt][2] = *(const uint32_t*)&Ah[r0 + kk + 8];
                    ah[mt][3] = *(const uint32_t*)&Ah[r0 + 8 * AST + kk + 8];
                    al[mt][0] = *(const uint32_t*)&Al[r0 + kk];
                    al[mt][1] = *(const uint32_t*)&Al[r0 + 8 * AST + kk];
                    al[mt][2] = *(const uint32_t*)&Al[r0 + kk + 8];
                    al[mt][3] = *(const uint32_t*)&Al[r0 + 8 * AST + kk + 8];
                }
                #pragma unroll
                for (int nt = 0; nt < 3; ++nt) {
                    const int nr = (n0 + nt * 8 + arow) * AST;
                    const uint32_t bh0 = *(const uint32_t*)&Bh[nr + kk];
                    const uint32_t bh1 = *(const uint32_t*)&Bh[nr + kk + 8];
                    const uint32_t bl0 = *(const uint32_t*)&Bl[nr + kk];
                    const uint32_t bl1 = *(const uint32_t*)&Bl[nr + kk + 8];
                    #pragma unroll
                    for (int mt = 0; mt < 2; ++mt) {
                        MMA(acc[mt][nt], ah[mt], bh0, bh1);
                        MMA(acc[mt][nt], ah[mt], bl0, bl1);
                        MMA(acc[mt][nt], al[mt], bh0, bh1);
                    }
                }
            }

            if (hp >= 2) BAR_SYNC(2 + buf * 4, 512);  // qt[buf] free (attention hp-2 done)

            // ---- epilogue: q*0.25 -> qt, k -> kt[t][d], v(ReLU) -> qt ----
            // Consuming all accs here also guarantees every B-fragment load has completed
            // before we signal B_FREE below (bar.arrive has no memory ordering).
            #pragma unroll
            for (int mt = 0; mt < 2; ++mt)
                #pragma unroll
                for (int nt = 0; nt < 3; ++nt) {
                    const int row0 = m0 + mt * 16 + arow, row1 = row0 + 8;
                    const int col  = n0 + nt * 8 + 2 * (lane & 3);
                    const int hh   = col / 48;
                    const int cls  = col % 48;
                    float c0 = acc[mt][nt][0], c1 = acc[mt][nt][1];
                    float c2 = acc[mt][nt][2], c3 = acc[mt][nt][3];
                    if (cls < 16) {
                        c0 *= 0.25f; c1 *= 0.25f; c2 *= 0.25f; c3 *= 0.25f;
                        float* r = qtb + (hh * 32 + cls) * QTS;
                        if (row0 < 49) { r[row0] = c0; r[QTS + row0] = c1; }
                        if (row1 < 49) { r[row1] = c2; r[QTS + row1] = c3; }
                    } else if (cls < 32) {
                        float* kb = ktb + hh * 49 * KTS + (cls - 16);
                        if (row0 < 49) { kb[row0 * KTS] = c0; kb[row0 * KTS + 1] = c1; }
                        if (row1 < 49) { kb[row1 * KTS] = c2; kb[row1 * KTS + 1] = c3; }
                    } else {
                        c0 = fmaxf(c0, 0.f); c1 = fmaxf(c1, 0.f);
                        c2 = fmaxf(c2, 0.f); c3 = fmaxf(c3, 0.f);
                        float* r = qtb + (hh * 32 + 16 + (cls - 32)) * QTS;
                        if (row0 < 49) { r[row0] = c0; r[QTS + row0] = c1; }
                        if (row1 < 49) { r[row1] = c2; r[QTS + row1] = c3; }
                    }
                }

            __threadfence_block();
            BAR_ARRIVE(1, 512);               // qt[buf] full
            if (hp < 7) BAR_ARRIVE(4, 512);   // B[hp] fully consumed (accs merged above)
        }
    }
}

extern "C" void kernel_launch(void* const* d_in, const int* in_sizes, int n_in,
                              void* d_out, int out_size) {
    const float* x   = (const float*)d_in[0];
    const float* g   = (const float*)d_in[1];
    const float* be  = (const float*)d_in[2];
    const float* mu  = (const float*)d_in[3];
    const float* var = (const float*)d_in[4];
    const float* qkw = (const float*)d_in[5];
    const float* vw  = (const float*)d_in[6];
    float* out = (float*)d_out;

    wconv_kernel<<<768, 256>>>(qkw, vw);
    cudaFuncSetAttribute(wsa_kernel, cudaFuncAttributeMaxDynamicSharedMemorySize, SMEM_TOTAL);
    wsa_kernel<<<4096, 512, SMEM_TOTAL>>>(x, g, be, mu, var, out);
}

// round 16
// speedup vs baseline: 1.2436x; 1.0071x over previous
#include <cuda_runtime.h>
#include <cuda_bf16.h>
#include <cstdint>

// bf16 HMMA (legacy mma.sync — available on plain compute_103 PTX, unlike tcgen05)
#define MMA(c, a, b0, b1) \
    asm volatile("mma.sync.aligned.m16n8k16.row.col.f32.bf16.bf16.f32 " \
        "{%0,%1,%2,%3}, {%4,%5,%6,%7}, {%8,%9}, {%0,%1,%2,%3};" \
        : "+f"((c)[0]), "+f"((c)[1]), "+f"((c)[2]), "+f"((c)[3]) \
        : "r"((a)[0]), "r"((a)[1]), "r"((a)[2]), "r"((a)[3]), "r"(b0), "r"(b1))

#define BAR_SYNC(id, cnt)   asm volatile("bar.sync %0, %1;"   :: "r"(id), "r"(cnt) : "memory")
#define BAR_ARRIVE(id, cnt) asm volatile("bar.arrive %0, %1;" :: "r"(id), "r"(cnt) : "memory")
// ids: 1=FULL(qt ready) 2=EMPTY buf0 6=EMPTY buf1 3=B_RDY 4=B_FREE 5=GEMM-init 7=ATT-internal
// All barriers strictly alternate producer-arrive / consumer-sync generations (audited).
// Key change vs r15: B_FREE arrives right after the GEMM mainloop (in-order issue per warp
// means all B-fragment LDS have landed in regs once the last MMA issued), and attention
// ISSUES next-B cp.async before waiting FULL, draining it after FULL — taking the weight
// LDG round-trip off the inter-hp critical path.

__device__ __forceinline__ void cp16(uint32_t dst, const void* src) {
    asm volatile("cp.async.cg.shared.global [%0], [%1], 16;" :: "r"(dst), "l"(src));
}
__device__ __forceinline__ uint32_t smem_u32(const void* p) {
    uint32_t a;
    asm("{ .reg .u64 t; cvta.to.shared.u64 t, %1; cvt.u32.u64 %0, t; }" : "=r"(a) : "l"(p));
    return a;
}

// Pre-converted weights: [hp][96 rows][256 k] bf16 hi / lo.
__device__ __nv_bfloat16 gWh[768 * 256];
__device__ __nv_bfloat16 gWl[768 * 256];

__global__ void wconv_kernel(const float* __restrict__ qkw, const float* __restrict__ vw) {
    const int g = blockIdx.x, k = threadIdx.x;
    const int hp = g / 96, r = g - hp * 96;
    const int hh = (r >= 48) ? 1 : 0;
    const int oc = r - 48 * hh;
    const int head = hp * 2 + hh;
    const float* src = (oc < 16) ? qkw + (head * 16 + oc) * 256
                     : (oc < 32) ? qkw + (256 + head * 16 + (oc - 16)) * 256
                                 : vw + (head * 16 + (oc - 32)) * 256;
    const float v = src[k];
    const __nv_bfloat16 h = __float2bfloat16(v);
    gWh[g * 256 + k] = h;
    gWl[g * 256 + k] = __float2bfloat16(v - __bfloat162float(h));
}

// Shapes: B=64, C=256, H=W=56, WS=7, HEADS=16, DH=16; 49 tokens/window (pad 64).
constexpr int AST = 264;                      // bf16 row stride (132 u32, %32==4 -> conflict-free frags)
constexpr int A_SZ = 64 * AST * 2;            // 33792
constexpr int B_SZ = 96 * AST * 2;            // 50688
constexpr int OFF_AH = 0;
constexpr int OFF_AL = OFF_AH + A_SZ;         // 33792
constexpr int OFF_BH = OFF_AL + A_SZ;         // 67584
constexpr int OFF_BL = OFF_BH + B_SZ;         // 118272
constexpr int OFF_QT = OFF_BL + B_SZ;         // 168960: qt[2 buf][64 rows][52] f32 (rows hh*32 + q0-15|v16-31)
constexpr int QTS   = 52;
constexpr int QT_BUF = 64 * QTS * 4;          // 13312
constexpr int OFF_KT = OFF_QT + 2 * QT_BUF;   // 195584: kt[2 buf][2 hh][49][20] f32
constexpr int KTS   = 20;
constexpr int KT_BUF = 2 * 49 * KTS * 4;      // 7840
constexpr int OFF_ST = OFF_KT + 2 * KT_BUF;   // 211264: st[2][49][50] f32
constexpr int SMEM_TOTAL = OFF_ST + 2 * 49 * 50 * 4;   // 230864

// Issue cp.async for head-pair hp's weights (hi+lo) with 256 attention threads. NON-blocking.
__device__ __forceinline__ void stage_weights256(uint32_t sb, int hp, int atid) {
    const __nv_bfloat16* srcH = gWh + hp * 96 * 256;
    const __nv_bfloat16* srcL = gWl + hp * 96 * 256;
    #pragma unroll
    for (int i = 0; i < 12; ++i) {
        const int idx = atid + i * 256;        // 0..3071: 96 rows x 32 chunks of 16 B
        const int r = idx >> 5, c8 = (idx & 31) * 8;
        cp16(sb + OFF_BH + (r * AST + c8) * 2, srcH + r * 256 + c8);
        cp16(sb + OFF_BL + (r * AST + c8) * 2, srcL + r * 256 + c8);
    }
    asm volatile("cp.async.commit_group;" ::: "memory");
}

__global__ __launch_bounds__(512, 1)
void wsa_kernel(const float* __restrict__ x,
                const float* __restrict__ bng, const float* __restrict__ bnb,
                const float* __restrict__ bnm, const float* __restrict__ bnv,
                float* __restrict__ out) {
    extern __shared__ char smem[];
    __nv_bfloat16* Ah = (__nv_bfloat16*)(smem + OFF_AH);
    __nv_bfloat16* Al = (__nv_bfloat16*)(smem + OFF_AL);
    __nv_bfloat16* Bh = (__nv_bfloat16*)(smem + OFF_BH);
    __nv_bfloat16* Bl = (__nv_bfloat16*)(smem + OFF_BL);
    float* st = (float*)(smem + OFF_ST);

    const uint32_t sb = smem_u32(smem);
    const int tid  = threadIdx.x;
    const int lane = tid & 31;
    const int warp = tid >> 5;
    const int wb   = blockIdx.x;
    const int b    = wb >> 6;
    const int n1   = (wb >> 3) & 7;
    const int n2   = wb & 7;
    float* outb = out + (size_t)b * 256 * 3136 + n1 * 56 + n2;

    if (warp >= 8) {
        // ===================== ATTENTION / STAGING GROUP (warps 8-15) =====================
        const int atid = tid - 256;
        const int aw   = warp - 8;

        // Prologue: stage B[0]; blocking drain; signal B_RDY.
        stage_weights256(sb, 0, atid);
        asm volatile("cp.async.wait_group 0;" ::: "memory");
        __threadfence_block();
        BAR_ARRIVE(3, 512);

        for (int hp = 0; hp < 8; ++hp) {
            const int buf = hp & 1;
            float* qtb = (float*)(smem + OFF_QT) + buf * 64 * QTS;
            float* ktb = (float*)(smem + OFF_KT) + buf * 2 * 49 * KTS;

            // Issue B[hp+1] staging as soon as GEMM is done READING B[hp] (mid-GEMM-hp).
            // LDG flight is hidden under GEMM's epilogue + our FULL wait.
            if (hp < 7) {
                BAR_SYNC(4, 512);             // GEMM finished reading B[hp]
                stage_weights256(sb, hp + 1, atid);   // non-blocking issue
            }

            BAR_SYNC(1, 512);                 // qt[buf] full (GEMM hp done)

            if (hp < 7) {                     // drain (mostly landed) + publish B[hp+1]
                asm volatile("cp.async.wait_group 0;" ::: "memory");
                __threadfence_block();
                BAR_ARRIVE(3, 512);           // GEMM(hp+1) starts NOW, overlapping S/softmax/PV
            }

            // ---- S = q @ k^T (0.25 pre-folded into q) ----
            {
                const int ah2 = aw >> 2, jg = aw & 3;
                const float* qb = qtb + (ah2 * 32) * QTS;
                const float* kb = ktb + ah2 * 49 * KTS;
                const bool act1 = (lane + 32) < 49;
                float q0[16], q1[16];
                #pragma unroll
                for (int dd = 0; dd < 16; ++dd) {
                    q0[dd] = qb[dd * QTS + lane];
                    q1[dd] = act1 ? qb[dd * QTS + lane + 32] : 0.f;
                }
                #pragma unroll
                for (int jj = 0; jj < 13; ++jj) {
                    const int j = jg * 13 + jj;
                    if (j < 49) {
                        float s0 = 0.f, s1 = 0.f;
                        #pragma unroll
                        for (int g = 0; g < 4; ++g) {
                            const float4 kv = *(const float4*)&kb[j * KTS + g * 4];  // broadcast
                            s0 = fmaf(kv.x, q0[g*4+0], s0); s1 = fmaf(kv.x, q1[g*4+0], s1);
                            s0 = fmaf(kv.y, q0[g*4+1], s0); s1 = fmaf(kv.y, q1[g*4+1], s1);
                            s0 = fmaf(kv.z, q0[g*4+2], s0); s1 = fmaf(kv.z, q1[g*4+2], s1);
                            s0 = fmaf(kv.w, q0[g*4+3], s0); s1 = fmaf(kv.w, q1[g*4+3], s1);
                        }
                        st[(ah2 * 49 + j) * 50 + lane] = s0;
                        if (act1) st[(ah2 * 49 + j) * 50 + lane + 32] = s1;
                    }
                }
            }
            BAR_SYNC(7, 256);

            // ---- softmax over j per query i (cols 0..97) ----
            if (atid < 98) {
                const int ah2 = atid >= 49;
                const int i   = atid - ah2 * 49;
                float* col = st + ah2 * 49 * 50 + i;
                float m = -1e30f;
                #pragma unroll 7
                for (int j = 0; j < 49; ++j) m = fmaxf(m, col[j * 50]);
                float sum = 0.f;
                #pragma unroll 7
                for (int j = 0; j < 49; ++j) {
                    const float e = __expf(col[j * 50] - m);
                    col[j * 50] = e;
                    sum += e;
                }
                const float rs = 1.f / sum;
                #pragma unroll 7
                for (int j = 0; j < 49; ++j) col[j * 50] *= rs;
            }
            BAR_SYNC(7, 256);

            // ---- O = P @ V -> scatter; each warp: 1 head x 4 d ----
            {
                const int ah2 = aw >> 2;
                const int d0  = (aw & 3) * 4;
                const float* pr = st + (ah2 * 49) * 50;
                const float* vr = qtb + (ah2 * 32 + 16 + d0) * QTS;
                const int head = hp * 2 + ah2;
                const bool act1 = (lane + 32) < 49;
                float o[4][2];
                #pragma unroll
                for (int e = 0; e < 4; ++e) { o[e][0] = 0.f; o[e][1] = 0.f; }
                #pragma unroll 3
                for (int jc = 0; jc < 48; jc += 4) {
                    float4 v[4];
                    #pragma unroll
                    for (int e = 0; e < 4; ++e) v[e] = *(const float4*)&vr[e * QTS + jc];
                    #pragma unroll
                    for (int e2 = 0; e2 < 4; ++e2) {
                        const int j = jc + e2;
                        const float p0 = pr[j * 50 + lane];
                        const float p1 = act1 ? pr[j * 50 + lane + 32] : 0.f;
                        #pragma unroll
                        for (int e = 0; e < 4; ++e) {
                            const float ve = (e2 == 0) ? v[e].x : (e2 == 1) ? v[e].y
                                          : (e2 == 2) ? v[e].z : v[e].w;
                            o[e][0] = fmaf(ve, p0, o[e][0]);
                            o[e][1] = fmaf(ve, p1, o[e][1]);
                        }
                    }
                }
                {   // j = 48 tail
                    const float p0 = pr[48 * 50 + lane];
                    const float p1 = act1 ? pr[48 * 50 + lane + 32] : 0.f;
                    #pragma unroll
                    for (int e = 0; e < 4; ++e) {
                        o[e][0] = fmaf(vr[e * QTS + 48], p0, o[e][0]);
                        o[e][1] = fmaf(vr[e * QTS + 48], p1, o[e][1]);
                    }
                }
                const int i0 = lane, ti0 = i0 / 7, tj0 = i0 - (i0 / 7) * 7;
                const int i1 = lane + 32, ti1 = i1 / 7, tj1 = i1 - (i1 / 7) * 7;
                #pragma unroll
                for (int e = 0; e < 4; ++e) {
                    const size_t ch = (size_t)(head * 16 + d0 + e) * 3136;
                    outb[ch + ti0 * 448 + tj0 * 8] = o[e][0];
                    if (act1) outb[ch + ti1 * 448 + tj1 * 8] = o[e][1];
                }
            }

            if (hp < 6) {                     // release qt[buf] (all qt/kt/st reads consumed above)
                __threadfence_block();
                BAR_ARRIVE(2 + buf * 4, 512); // 2: buf0, 6: buf1
            }
        }
    } else {
        // ===================== GEMM GROUP (warps 0-7) =====================
        // Stage A: channel c = tid (0..255), all 49 tokens, bf16 hi/lo split.
        {
            const int c = tid;
            const float inv = bng[c] / sqrtf(bnv[c] + 1e-6f);
            const float shf = bnb[c] - bnm[c] * inv;
            const float* xb = x + ((size_t)b * 256 + c) * 3136 + n1 * 56 + n2;
            #pragma unroll 7
            for (int t = 0; t < 49; ++t) {
                const int ti = t / 7, tj = t - (t / 7) * 7;
                const float v = fmaf(xb[ti * 448 + tj * 8], inv, shf);
                const __nv_bfloat16 h = __float2bfloat16(v);
                Ah[t * AST + c] = h;
                Al[t * AST + c] = __float2bfloat16(v - __bfloat162float(h));
            }
            for (int i = tid; i < 15 * 128; i += 256) {     // zero pad rows 49..63 (k 0..255)
                const int row = 49 + (i >> 7), cc = (i & 127) * 2;
                *(uint32_t*)&Ah[row * AST + cc] = 0u;
                *(uint32_t*)&Al[row * AST + cc] = 0u;
            }
        }
        BAR_SYNC(5, 256);                     // A visible to all GEMM warps

        const int m0 = (warp & 1) * 32;
        const int n0 = (warp >> 1) * 24;
        const int arow = lane >> 2;

        for (int hp = 0; hp < 8; ++hp) {
            const int buf = hp & 1;
            float* qtb = (float*)(smem + OFF_QT) + buf * 64 * QTS;
            float* ktb = (float*)(smem + OFF_KT) + buf * 2 * 49 * KTS;

            BAR_SYNC(3, 512);                 // B[hp] staged

            float acc[2][3][4];
            #pragma unroll
            for (int mt = 0; mt < 2; ++mt)
                #pragma unroll
                for (int nt = 0; nt < 3; ++nt)
                    #pragma unroll
                    for (int e = 0; e < 4; ++e) acc[mt][nt][e] = 0.f;

            #pragma unroll 2
            for (int ks = 0; ks < 16; ++ks) {
                const int kk = ks * 16 + 2 * (lane & 3);
                uint32_t ah[2][4], al[2][4];
                #pragma unroll
                for (int mt = 0; mt < 2; ++mt) {
                    const int r0 = (m0 + mt * 16 + arow) * AST;
                    ah[mt][0] = *(const uint32_t*)&Ah[r0 + kk];
                    ah[mt][1] = *(const uint32_t*)&Ah[r0 + 8 * AST + kk];
                    ah[mt][2] = *(const uint32_t*)&Ah[r0 + kk + 8];
                    ah[mt][3] = *(const uint32_t*)&Ah[r0 + 8 * AST + kk + 8];
                    al[mt][0] = *(const uint32_t*)&Al[r0 + kk];
                    al[mt][1] = *(const uint32_t*)&Al[r0 + 8 * AST + kk];
                    al[mt][2] = *(const uint32_t*)&Al[r0 + kk + 8];
                    al[mt][3] = *(const uint32_t*)&Al[r0 + 8 * AST + kk + 8];
                }
                #pragma unroll
                for (int nt = 0; nt < 3; ++nt) {
                    const int nr = (n0 + nt * 8 + arow) * AST;
                    const uint32_t bh0 = *(const uint32_t*)&Bh[nr + kk];
                    const uint32_t bh1 = *(const uint32_t*)&Bh[nr + kk + 8];
                    const uint32_t bl0 = *(const uint32_t*)&Bl[nr + kk];
                    const uint32_t bl1 = *(const uint32_t*)&Bl[nr + kk + 8];
                    #pragma unroll
                    for (int mt = 0; mt < 2; ++mt) {
                        MMA(acc[mt][nt], ah[mt], bh0, bh1);
                        MMA(acc[mt][nt], ah[mt], bl0, bl1);
                        MMA(acc[mt][nt], al[mt], bh0, bh1);
                    }
                }
            }

            // B[hp] fully consumed: per-warp in-order issue means the last MMA issuing
            // implies all B-fragment LDS data already landed in registers.
            if (hp < 7) BAR_ARRIVE(4, 512);

            if (hp >= 2) BAR_SYNC(2 + buf * 4, 512);  // qt[buf] free (attention hp-2 done)

            // ---- epilogue: q*0.25 -> qt, k -> kt[t][d], v(ReLU) -> qt ----
            #pragma unroll
            for (int mt = 0; mt < 2; ++mt)
                #pragma unroll
                for (int nt = 0; nt < 3; ++nt) {
                    const int row0 = m0 + mt * 16 + arow, row1 = row0 + 8;
                    const int col  = n0 + nt * 8 + 2 * (lane & 3);
                    const int hh   = col / 48;
                    const int cls  = col % 48;
                    float c0 = acc[mt][nt][0], c1 = acc[mt][nt][1];
                    float c2 = acc[mt][nt][2], c3 = acc[mt][nt][3];
                    if (cls < 16) {
                        c0 *= 0.25f; c1 *= 0.25f; c2 *= 0.25f; c3 *= 0.25f;
                        float* r = qtb + (hh * 32 + cls) * QTS;
                        if (row0 < 49) { r[row0] = c0; r[QTS + row0] = c1; }
                        if (row1 < 49) { r[row1] = c2; r[QTS + row1] = c3; }
                    } else if (cls < 32) {
                        float* kb = ktb + hh * 49 * KTS + (cls - 16);
                        if (row0 < 49) { kb[row0 * KTS] = c0; kb[row0 * KTS + 1] = c1; }
                        if (row1 < 49) { kb[row1 * KTS] = c2; kb[row1 * KTS + 1] = c3; }
                    } else {
                        c0 = fmaxf(c0, 0.f); c1 = fmaxf(c1, 0.f);
                        c2 = fmaxf(c2, 0.f); c3 = fmaxf(c3, 0.f);
                        float* r = qtb + (hh * 32 + 16 + (cls - 32)) * QTS;
                        if (row0 < 49) { r[row0] = c0; r[QTS + row0] = c1; }
                        if (row1 < 49) { r[row1] = c2; r[QTS + row1] = c3; }
                    }
                }

            __threadfence_block();
            BAR_ARRIVE(1, 512);               // qt[buf] full
        }
    }
}

extern "C" void kernel_launch(void* const* d_in, const int* in_sizes, int n_in,
                              void* d_out, int out_size) {
    const float* x   = (const float*)d_in[0];
    const float* g   = (const float*)d_in[1];
    const float* be  = (const float*)d_in[2];
    const float* mu  = (const float*)d_in[3];
    const float* var = (const float*)d_in[4];
    const float* qkw = (const float*)d_in[5];
    const float* vw  = (const float*)d_in[6];
    float* out = (float*)d_out;

    wconv_kernel<<<768, 256>>>(qkw, vw);
    cudaFuncSetAttribute(wsa_kernel, cudaFuncAttributeMaxDynamicSharedMemorySize, SMEM_TOTAL);
    wsa_kernel<<<4096, 512, SMEM_TOTAL>>>(x, g, be, mu, var, out);
}

// round 17
// speedup vs baseline: 1.2448x; 1.0010x over previous
#include <cuda_runtime.h>
#include <cuda_bf16.h>
#include <cstdint>

// bf16 HMMA (legacy mma.sync — available on plain compute_103 PTX, unlike tcgen05)
#define MMA(c, a, b0, b1) \
    asm volatile("mma.sync.aligned.m16n8k16.row.col.f32.bf16.bf16.f32 " \
        "{%0,%1,%2,%3}, {%4,%5,%6,%7}, {%8,%9}, {%0,%1,%2,%3};" \
        : "+f"((c)[0]), "+f"((c)[1]), "+f"((c)[2]), "+f"((c)[3]) \
        : "r"((a)[0]), "r"((a)[1]), "r"((a)[2]), "r"((a)[3]), "r"(b0), "r"(b1))

#define LDSM4(r, addr) \
    asm volatile("ldmatrix.sync.aligned.m8n8.x4.shared.b16 {%0,%1,%2,%3}, [%4];" \
        : "=r"((r)[0]), "=r"((r)[1]), "=r"((r)[2]), "=r"((r)[3]) : "r"(addr))
#define LDSM2(r0, r1, addr) \
    asm volatile("ldmatrix.sync.aligned.m8n8.x2.shared.b16 {%0,%1}, [%2];" \
        : "=r"(r0), "=r"(r1) : "r"(addr))

#define BAR_SYNC(id, cnt)   asm volatile("bar.sync %0, %1;"   :: "r"(id), "r"(cnt) : "memory")
#define BAR_ARRIVE(id, cnt) asm volatile("bar.arrive %0, %1;" :: "r"(id), "r"(cnt) : "memory")
// ids: 1=FULL(qt ready) 2=EMPTY buf0 6=EMPTY buf1 3=B_RDY 4=B_FREE 5=GEMM-init 7=ATT-internal

__device__ __forceinline__ void cp16(uint32_t dst, const void* src) {
    asm volatile("cp.async.cg.shared.global [%0], [%1], 16;" :: "r"(dst), "l"(src));
}
__device__ __forceinline__ uint32_t smem_u32(const void* p) {
    uint32_t a;
    asm("{ .reg .u64 t; cvta.to.shared.u64 t, %1; cvt.u32.u64 %0, t; }" : "=r"(a) : "l"(p));
    return a;
}

// Pre-converted weights: [hp][96 rows][256 k] bf16 hi / lo.
__device__ __nv_bfloat16 gWh[768 * 256];
__device__ __nv_bfloat16 gWl[768 * 256];

__global__ void wconv_kernel(const float* __restrict__ qkw, const float* __restrict__ vw) {
    const int g = blockIdx.x, k = threadIdx.x;
    const int hp = g / 96, r = g - hp * 96;
    const int hh = (r >= 48) ? 1 : 0;
    const int oc = r - 48 * hh;
    const int head = hp * 2 + hh;
    const float* src = (oc < 16) ? qkw + (head * 16 + oc) * 256
                     : (oc < 32) ? qkw + (256 + head * 16 + (oc - 16)) * 256
                                 : vw + (head * 16 + (oc - 32)) * 256;
    const float v = src[k];
    const __nv_bfloat16 h = __float2bfloat16(v);
    gWh[g * 256 + k] = h;
    gWl[g * 256 + k] = __float2bfloat16(v - __bfloat162float(h));
}

// Shapes: B=64, C=256, H=W=56, WS=7, HEADS=16, DH=16; 49 tokens/window (pad 64).
constexpr int AST = 264;                      // bf16 row stride: 528 B (16B-aligned; 132 words, %32==4)
constexpr int A_SZ = 64 * AST * 2;            // 33792
constexpr int B_SZ = 96 * AST * 2;            // 50688
constexpr int OFF_AH = 0;
constexpr int OFF_AL = OFF_AH + A_SZ;         // 33792
constexpr int OFF_BH = OFF_AL + A_SZ;         // 67584
constexpr int OFF_BL = OFF_BH + B_SZ;         // 118272
constexpr int OFF_QT = OFF_BL + B_SZ;         // 168960: qt[2 buf][64 rows][52] f32 (rows hh*32 + q0-15|v16-31)
constexpr int QTS   = 52;
constexpr int QT_BUF = 64 * QTS * 4;          // 13312
constexpr int OFF_KT = OFF_QT + 2 * QT_BUF;   // 195584: kt[2 buf][2 hh][49][20] f32
constexpr int KTS   = 20;
constexpr int KT_BUF = 2 * 49 * KTS * 4;      // 7840
constexpr int OFF_ST = OFF_KT + 2 * KT_BUF;   // 211264: st[2][49][50] f32
constexpr int SMEM_TOTAL = OFF_ST + 2 * 49 * 50 * 4;   // 230864

// Issue cp.async for head-pair hp's weights (hi+lo) with 256 attention threads. NON-blocking.
__device__ __forceinline__ void stage_weights256(uint32_t sb, int hp, int atid) {
    const __nv_bfloat16* srcH = gWh + hp * 96 * 256;
    const __nv_bfloat16* srcL = gWl + hp * 96 * 256;
    #pragma unroll
    for (int i = 0; i < 12; ++i) {
        const int idx = atid + i * 256;        // 0..3071: 96 rows x 32 chunks of 16 B
        const int r = idx >> 5, c8 = (idx & 31) * 8;
        cp16(sb + OFF_BH + (r * AST + c8) * 2, srcH + r * 256 + c8);
        cp16(sb + OFF_BL + (r * AST + c8) * 2, srcL + r * 256 + c8);
    }
    asm volatile("cp.async.commit_group;" ::: "memory");
}

__global__ __launch_bounds__(512, 1)
void wsa_kernel(const float* __restrict__ x,
                const float* __restrict__ bng, const float* __restrict__ bnb,
                const float* __restrict__ bnm, const float* __restrict__ bnv,
                float* __restrict__ out) {
    extern __shared__ char smem[];
    __nv_bfloat16* Ah = (__nv_bfloat16*)(smem + OFF_AH);
    __nv_bfloat16* Al = (__nv_bfloat16*)(smem + OFF_AL);
    float* st = (float*)(smem + OFF_ST);

    const uint32_t sb = smem_u32(smem);
    const int tid  = threadIdx.x;
    const int lane = tid & 31;
    const int warp = tid >> 5;
    const int wb   = blockIdx.x;
    const int b    = wb >> 6;
    const int n1   = (wb >> 3) & 7;
    const int n2   = wb & 7;
    float* outb = out + (size_t)b * 256 * 3136 + n1 * 56 + n2;

    if (warp >= 8) {
        // ===================== ATTENTION / STAGING GROUP (warps 8-15) =====================
        const int atid = tid - 256;
        const int aw   = warp - 8;

        // Prologue: stage B[0]; blocking drain; signal B_RDY.
        stage_weights256(sb, 0, atid);
        asm volatile("cp.async.wait_group 0;" ::: "memory");
        __threadfence_block();
        BAR_ARRIVE(3, 512);

        for (int hp = 0; hp < 8; ++hp) {
            const int buf = hp & 1;
            float* qtb = (float*)(smem + OFF_QT) + buf * 64 * QTS;
            float* ktb = (float*)(smem + OFF_KT) + buf * 2 * 49 * KTS;

            // Issue B[hp+1] staging as soon as GEMM is done READING B[hp].
            if (hp < 7) {
                BAR_SYNC(4, 512);             // GEMM finished reading B[hp]
                stage_weights256(sb, hp + 1, atid);   // non-blocking issue
            }

            BAR_SYNC(1, 512);                 // qt[buf] full (GEMM hp done)

            if (hp < 7) {                     // drain (mostly landed) + publish B[hp+1]
                asm volatile("cp.async.wait_group 0;" ::: "memory");
                __threadfence_block();
                BAR_ARRIVE(3, 512);           // GEMM(hp+1) starts, overlapping S/softmax/PV
            }

            // ---- S = q @ k^T (0.25 pre-folded into q) ----
            {
                const int ah2 = aw >> 2, jg = aw & 3;
                const float* qb = qtb + (ah2 * 32) * QTS;
                const float* kb = ktb + ah2 * 49 * KTS;
                const bool act1 = (lane + 32) < 49;
                float q0[16], q1[16];
                #pragma unroll
                for (int dd = 0; dd < 16; ++dd) {
                    q0[dd] = qb[dd * QTS + lane];
                    q1[dd] = act1 ? qb[dd * QTS + lane + 32] : 0.f;
                }
                #pragma unroll
                for (int jj = 0; jj < 13; ++jj) {
                    const int j = jg * 13 + jj;
                    if (j < 49) {
                        float s0 = 0.f, s1 = 0.f;
                        #pragma unroll
                        for (int g = 0; g < 4; ++g) {
                            const float4 kv = *(const float4*)&kb[j * KTS + g * 4];  // broadcast
                            s0 = fmaf(kv.x, q0[g*4+0], s0); s1 = fmaf(kv.x, q1[g*4+0], s1);
                            s0 = fmaf(kv.y, q0[g*4+1], s0); s1 = fmaf(kv.y, q1[g*4+1], s1);
                            s0 = fmaf(kv.z, q0[g*4+2], s0); s1 = fmaf(kv.z, q1[g*4+2], s1);
                            s0 = fmaf(kv.w, q0[g*4+3], s0); s1 = fmaf(kv.w, q1[g*4+3], s1);
                        }
                        st[(ah2 * 49 + j) * 50 + lane] = s0;
                        if (act1) st[(ah2 * 49 + j) * 50 + lane + 32] = s1;
                    }
                }
            }
            BAR_SYNC(7, 256);

            // ---- softmax over j per query i (cols 0..97) ----
            if (atid < 98) {
                const int ah2 = atid >= 49;
                const int i   = atid - ah2 * 49;
                float* col = st + ah2 * 49 * 50 + i;
                float m = -1e30f;
                #pragma unroll 7
                for (int j = 0; j < 49; ++j) m = fmaxf(m, col[j * 50]);
                float sum = 0.f;
                #pragma unroll 7
                for (int j = 0; j < 49; ++j) {
                    const float e = __expf(col[j * 50] - m);
                    col[j * 50] = e;
                    sum += e;
                }
                const float rs = 1.f / sum;
                #pragma unroll 7
                for (int j = 0; j < 49; ++j) col[j * 50] *= rs;
            }
            BAR_SYNC(7, 256);

            // ---- O = P @ V -> scatter; each warp: 1 head x 4 d ----
            {
                const int ah2 = aw >> 2;
                const int d0  = (aw & 3) * 4;
                const float* pr = st + (ah2 * 49) * 50;
                const float* vr = qtb + (ah2 * 32 + 16 + d0) * QTS;
                const int head = hp * 2 + ah2;
                const bool act1 = (lane + 32) < 49;
                float o[4][2];
                #pragma unroll
                for (int e = 0; e < 4; ++e) { o[e][0] = 0.f; o[e][1] = 0.f; }
                #pragma unroll 3
                for (int jc = 0; jc < 48; jc += 4) {
                    float4 v[4];
                    #pragma unroll
                    for (int e = 0; e < 4; ++e) v[e] = *(const float4*)&vr[e * QTS + jc];
                    #pragma unroll
                    for (int e2 = 0; e2 < 4; ++e2) {
                        const int j = jc + e2;
                        const float p0 = pr[j * 50 + lane];
                        const float p1 = act1 ? pr[j * 50 + lane + 32] : 0.f;
                        #pragma unroll
                        for (int e = 0; e < 4; ++e) {
                            const float ve = (e2 == 0) ? v[e].x : (e2 == 1) ? v[e].y
                                          : (e2 == 2) ? v[e].z : v[e].w;
                            o[e][0] = fmaf(ve, p0, o[e][0]);
                            o[e][1] = fmaf(ve, p1, o[e][1]);
                        }
                    }
                }
                {   // j = 48 tail
                    const float p0 = pr[48 * 50 + lane];
                    const float p1 = act1 ? pr[48 * 50 + lane + 32] : 0.f;
                    #pragma unroll
                    for (int e = 0; e < 4; ++e) {
                        o[e][0] = fmaf(vr[e * QTS + 48], p0, o[e][0]);
                        o[e][1] = fmaf(vr[e * QTS + 48], p1, o[e][1]);
                    }
                }
                const int i0 = lane, ti0 = i0 / 7, tj0 = i0 - (i0 / 7) * 7;
                const int i1 = lane + 32, ti1 = i1 / 7, tj1 = i1 - (i1 / 7) * 7;
                #pragma unroll
                for (int e = 0; e < 4; ++e) {
                    const size_t ch = (size_t)(head * 16 + d0 + e) * 3136;
                    outb[ch + ti0 * 448 + tj0 * 8] = o[e][0];
                    if (act1) outb[ch + ti1 * 448 + tj1 * 8] = o[e][1];
                }
            }

            if (hp < 6) {                     // release qt[buf]
                __threadfence_block();
                BAR_ARRIVE(2 + buf * 4, 512); // 2: buf0, 6: buf1
            }
        }
    } else {
        // ===================== GEMM GROUP (warps 0-7) =====================
        // Stage A: channel c = tid (0..255), all 49 tokens, bf16 hi/lo split.
        {
            const int c = tid;
            const float inv = bng[c] / sqrtf(bnv[c] + 1e-6f);
            const float shf = bnb[c] - bnm[c] * inv;
            const float* xb = x + ((size_t)b * 256 + c) * 3136 + n1 * 56 + n2;
            #pragma unroll 7
            for (int t = 0; t < 49; ++t) {
                const int ti = t / 7, tj = t - (t / 7) * 7;
                const float v = fmaf(xb[ti * 448 + tj * 8], inv, shf);
                const __nv_bfloat16 h = __float2bfloat16(v);
                Ah[t * AST + c] = h;
                Al[t * AST + c] = __float2bfloat16(v - __bfloat162float(h));
            }
            for (int i = tid; i < 15 * 128; i += 256) {     // zero pad rows 49..63 (k 0..255)
                const int row = 49 + (i >> 7), cc = (i & 127) * 2;
                *(uint32_t*)&Ah[row * AST + cc] = 0u;
                *(uint32_t*)&Al[row * AST + cc] = 0u;
            }
        }
        BAR_SYNC(5, 256);                     // A visible to all GEMM warps

        const int m0 = (warp & 1) * 32;
        const int n0 = (warp >> 1) * 24;
        const int arow = lane >> 2;

        // ---- ldmatrix per-lane base addresses (byte offsets into smem) ----
        // A x4 (m16k16): lanes 0-15 -> rows m+0..15 at k+0; lanes 16-31 -> same rows at k+8.
        const int aoff = ((m0 + (lane & 15)) * AST + (lane >> 4) * 8) * 2;
        const uint32_t aH0 = sb + OFF_AH + aoff;
        const uint32_t aH1 = aH0 + 16 * AST * 2;
        const uint32_t aL0 = sb + OFF_AL + aoff;
        const uint32_t aL1 = aL0 + 16 * AST * 2;
        // B x4 (two n8k16 tiles nt0/nt1): g=lane>>3: g0 nt0@k0, g1 nt0@k8, g2 nt1@k0, g3 nt1@k8.
        const int bg = lane >> 3, bl7 = lane & 7;
        const int boff01 = ((n0 + ((bg & 2) ? 8 : 0) + bl7) * AST + (bg & 1) * 8) * 2;
        const uint32_t bH01 = sb + OFF_BH + boff01;
        const uint32_t bL01 = sb + OFF_BL + boff01;
        // B x2 (nt2): lanes 0-7 rows@k0, lanes 8-15 rows@k8 (upper lanes ignored).
        const int boff2 = ((n0 + 16 + bl7) * AST + (bg & 1) * 8) * 2;
        const uint32_t bH2 = sb + OFF_BH + boff2;
        const uint32_t bL2 = sb + OFF_BL + boff2;

        for (int hp = 0; hp < 8; ++hp) {
            const int buf = hp & 1;
            float* qtb = (float*)(smem + OFF_QT) + buf * 64 * QTS;
            float* ktb = (float*)(smem + OFF_KT) + buf * 2 * 49 * KTS;

            BAR_SYNC(3, 512);                 // B[hp] staged

            float acc[2][3][4];
            #pragma unroll
            for (int mt = 0; mt < 2; ++mt)
                #pragma unroll
                for (int nt = 0; nt < 3; ++nt)
                    #pragma unroll
                    for (int e = 0; e < 4; ++e) acc[mt][nt][e] = 0.f;

            #pragma unroll 2
            for (int ks = 0; ks < 16; ++ks) {
                const uint32_t ko = ks * 32;  // 16 bf16 = 32 bytes per k-step
                uint32_t ah[2][4], al[2][4], b01h[4], b01l[4], b2h[2], b2l[2];
                LDSM4(ah[0], aH0 + ko);
                LDSM4(ah[1], aH1 + ko);
                LDSM4(al[0], aL0 + ko);
                LDSM4(al[1], aL1 + ko);
                LDSM4(b01h, bH01 + ko);
                LDSM4(b01l, bL01 + ko);
                LDSM2(b2h[0], b2h[1], bH2 + ko);
                LDSM2(b2l[0], b2l[1], bL2 + ko);
                #pragma unroll
                for (int mt = 0; mt < 2; ++mt) {
                    MMA(acc[mt][0], ah[mt], b01h[0], b01h[1]);
                    MMA(acc[mt][0], ah[mt], b01l[0], b01l[1]);
                    MMA(acc[mt][0], al[mt], b01h[0], b01h[1]);
                    MMA(acc[mt][1], ah[mt], b01h[2], b01h[3]);
                    MMA(acc[mt][1], ah[mt], b01l[2], b01l[3]);
                    MMA(acc[mt][1], al[mt], b01h[2], b01h[3]);
                    MMA(acc[mt][2], ah[mt], b2h[0], b2h[1]);
                    MMA(acc[mt][2], ah[mt], b2l[0], b2l[1]);
                    MMA(acc[mt][2], al[mt], b2h[0], b2h[1]);
                }
            }

            // B[hp] fully consumed (per-warp in-order issue: data in regs once last MMA issued).
            if (hp < 7) BAR_ARRIVE(4, 512);

            if (hp >= 2) BAR_SYNC(2 + buf * 4, 512);  // qt[buf] free (attention hp-2 done)

            // ---- epilogue: q*0.25 -> qt, k -> kt[t][d], v(ReLU) -> qt ----
            #pragma unroll
            for (int mt = 0; mt < 2; ++mt)
                #pragma unroll
                for (int nt = 0; nt < 3; ++nt) {
                    const int row0 = m0 + mt * 16 + arow, row1 = row0 + 8;
                    const int col  = n0 + nt * 8 + 2 * (lane & 3);
                    const int hh   = col / 48;
                    const int cls  = col % 48;
                    float c0 = acc[mt][nt][0], c1 = acc[mt][nt][1];
                    float c2 = acc[mt][nt][2], c3 = acc[mt][nt][3];
                    if (cls < 16) {
                        c0 *= 0.25f; c1 *= 0.25f; c2 *= 0.25f; c3 *= 0.25f;
                        float* r = qtb + (hh * 32 + cls) * QTS;
                        if (row0 < 49) { r[row0] = c0; r[QTS + row0] = c1; }
                        if (row1 < 49) { r[row1] = c2; r[QTS + row1] = c3; }
                    } else if (cls < 32) {
                        float* kb = ktb + hh * 49 * KTS + (cls - 16);
                        if (row0 < 49) { kb[row0 * KTS] = c0; kb[row0 * KTS + 1] = c1; }
                        if (row1 < 49) { kb[row1 * KTS] = c2; kb[row1 * KTS + 1] = c3; }
                    } else {
                        c0 = fmaxf(c0, 0.f); c1 = fmaxf(c1, 0.f);
                        c2 = fmaxf(c2, 0.f); c3 = fmaxf(c3, 0.f);
                        float* r = qtb + (hh * 32 + 16 + (cls - 32)) * QTS;
                        if (row0 < 49) { r[row0] = c0; r[QTS + row0] = c1; }
                        if (row1 < 49) { r[row1] = c2; r[QTS + row1] = c3; }
                    }
                }

            __threadfence_block();
            BAR_ARRIVE(1, 512);               // qt[buf] full
        }
    }
}

extern "C" void kernel_launch(void* const* d_in, const int* in_sizes, int n_in,
                              void* d_out, int out_size) {
    const float* x   = (const float*)d_in[0];
    const float* g   = (const float*)d_in[1];
    const float* be  = (const float*)d_in[2];
    const float* mu  = (const float*)d_in[3];
    const float* var = (const float*)d_in[4];
    const float* qkw = (const float*)d_in[5];
    const float* vw  = (const float*)d_in[6];
    float* out = (float*)d_out;

    wconv_kernel<<<768, 256>>>(qkw, vw);
    cudaFuncSetAttribute(wsa_kernel, cudaFuncAttributeMaxDynamicSharedMemorySize, SMEM_TOTAL);
    wsa_kernel<<<4096, 512, SMEM_TOTAL>>>(x, g, be, mu, var, out);
}